// round 2
// baseline (speedup 1.0000x reference)
#include <cuda_runtime.h>

// Spectral_Pool: out[b,k1,k2,c] = sum_{n1,n2} A[k1,n1]A[k2,n2] x[b,n1,n2,c]
//                                 - B[k1,n1]B[k2,n2] x[b,n1,n2,c]
// A = D * cos(2*pi*n/256), B = D * sin(2*pi*n/256)
// D[k,n] = (1/217) * sin(217*phi/2)/sin(phi/2), phi = 2*pi*(k/217 - n/256)

namespace {
constexpr int Hn = 256;   // input spatial size
constexpr int Kc = 217;   // output spatial size (int(0.85*256))
constexpr int Bt = 16;    // batch
constexpr int Ch = 64;    // channels
constexpr int R1 = 2 * Kc;        // 434 stacked rows [A;B]
constexpr int NC = Hn * Ch;       // 16384 (n2,c folded)
constexpr double PI_D = 3.14159265358979323846;
}

// Scratch / tables as device globals (no allocations allowed in kernel_launch)
__device__ float g_W1[R1 * Hn];              // [434][256] rows 0..216 = A, 217..433 = B
__device__ float g_W2[Kc * 2 * Hn];          // [217][512] = [A | -B]
__device__ float g_Y[(size_t)Bt * R1 * NC];  // stage-1 output: [b][r][n2*64+c]

// ---------------------------------------------------------------------------
// Table init: 217*256 threads, double-precision trig for accurate tables.
// ---------------------------------------------------------------------------
__global__ void sp_init() {
    int idx = blockIdx.x * blockDim.x + threadIdx.x;
    if (idx >= Kc * Hn) return;
    int k = idx / Hn;
    int n = idx - k * Hn;
    double ph = PI_D * ((double)k / (double)Kc - (double)n / (double)Hn);
    double D;
    if (k == 0 && n == 0) {
        D = 1.0;  // Dirichlet kernel limit at phi = 0
    } else {
        D = sin(217.0 * ph) / (sin(ph) * 217.0);
    }
    double ang = 2.0 * PI_D * (double)n / (double)Hn;
    float a = (float)(D * cos(ang));
    float b = (float)(D * sin(ang));
    g_W1[k * Hn + n]        = a;
    g_W1[(k + Kc) * Hn + n] = b;
    g_W2[k * (2 * Hn) + n]      = a;
    g_W2[k * (2 * Hn) + Hn + n] = -b;
}

// ---------------------------------------------------------------------------
// Stage 1: per-b GEMM  Y[b] (434 x 16384) = W1 (434 x 256) * X[b] (256 x 16384)
// 128x128x8 tiles, 256 threads, 8x8 per thread.
// ---------------------------------------------------------------------------
constexpr int BM1 = 128, BN1 = 128, BK1 = 8;

__global__ __launch_bounds__(256) void sp_stage1(const float* __restrict__ X) {
    __shared__ float As[BK1][BM1 + 4];
    __shared__ float Bs[BK1][BN1 + 4];

    const int b     = blockIdx.z;
    const int mbase = blockIdx.y * BM1;
    const int nbase = blockIdx.x * BN1;
    const float* __restrict__ Xb = X + (size_t)b * Hn * NC;
    float* __restrict__ Yb = g_Y + (size_t)b * R1 * NC;

    const int tid  = threadIdx.x;
    const int arow = tid >> 1;          // 0..127
    const int acol = (tid & 1) * 4;     // 0 or 4
    const int brow = tid >> 5;          // 0..7
    const int bcol = (tid & 31) * 4;    // 0..124
    const int ty   = tid >> 4;          // 0..15
    const int tx   = tid & 15;          // 0..15

    float acc[8][8];
#pragma unroll
    for (int i = 0; i < 8; i++)
#pragma unroll
        for (int j = 0; j < 8; j++) acc[i][j] = 0.f;

    for (int k0 = 0; k0 < Hn; k0 += BK1) {
        // Load W1 tile (transpose into As[k][m])
        {
            int gr = mbase + arow;
            float4 av = make_float4(0.f, 0.f, 0.f, 0.f);
            if (gr < R1) av = *(const float4*)(&g_W1[gr * Hn + k0 + acol]);
            As[acol + 0][arow] = av.x;
            As[acol + 1][arow] = av.y;
            As[acol + 2][arow] = av.z;
            As[acol + 3][arow] = av.w;
        }
        // Load X tile
        *(float4*)(&Bs[brow][bcol]) =
            *(const float4*)(&Xb[(size_t)(k0 + brow) * NC + nbase + bcol]);
        __syncthreads();

#pragma unroll
        for (int p = 0; p < BK1; p++) {
            float4 a0 = *(const float4*)(&As[p][ty * 8]);
            float4 a1 = *(const float4*)(&As[p][ty * 8 + 4]);
            float4 b0 = *(const float4*)(&Bs[p][tx * 8]);
            float4 b1 = *(const float4*)(&Bs[p][tx * 8 + 4]);
            float ra[8] = {a0.x, a0.y, a0.z, a0.w, a1.x, a1.y, a1.z, a1.w};
            float rb[8] = {b0.x, b0.y, b0.z, b0.w, b1.x, b1.y, b1.z, b1.w};
#pragma unroll
            for (int i = 0; i < 8; i++)
#pragma unroll
                for (int j = 0; j < 8; j++) acc[i][j] += ra[i] * rb[j];
        }
        __syncthreads();
    }

#pragma unroll
    for (int i = 0; i < 8; i++) {
        int r = mbase + ty * 8 + i;
        if (r < R1) {
            float* dst = &Yb[(size_t)r * NC + nbase + tx * 8];
            *(float4*)(dst)     = make_float4(acc[i][0], acc[i][1], acc[i][2], acc[i][3]);
            *(float4*)(dst + 4) = make_float4(acc[i][4], acc[i][5], acc[i][6], acc[i][7]);
        }
    }
}

// ---------------------------------------------------------------------------
// Stage 2: batched over (b, k1):
//   out[b,k1,k2,c] = sum_{kk<512} W2[k2,kk] * V[kk,c]
//   V[kk,c] = Y[b, k1,      kk,     c]  (kk < 256)
//           = Y[b, 217+k1,  kk-256, c]  (kk >= 256)
// 64x64x16 tiles, 256 threads, 4x4 per thread. Grid (4, 217, 16).
// ---------------------------------------------------------------------------
constexpr int BM2 = 64, BN2 = 64, BK2 = 16;

__global__ __launch_bounds__(256) void sp_stage2(float* __restrict__ out) {
    __shared__ float Ws[BK2][BM2 + 4];
    __shared__ float Vs[BK2][BN2 + 4];

    const int mbase = blockIdx.x * BM2;
    const int k1    = blockIdx.y;
    const int b     = blockIdx.z;
    const float* __restrict__ Ya  = g_Y + (size_t)(b * R1 + k1) * NC;
    const float* __restrict__ Yb2 = g_Y + (size_t)(b * R1 + Kc + k1) * NC;

    const int tid  = threadIdx.x;
    const int wrow = tid >> 2;          // 0..63
    const int wcol = (tid & 3) * 4;     // 0..12
    const int vrow = tid >> 4;          // 0..15
    const int vcol = (tid & 15) * 4;    // 0..60
    const int ty   = tid >> 4;
    const int tx   = tid & 15;

    float acc[4][4];
#pragma unroll
    for (int i = 0; i < 4; i++)
#pragma unroll
        for (int j = 0; j < 4; j++) acc[i][j] = 0.f;

    for (int k0 = 0; k0 < 2 * Hn; k0 += BK2) {
        // W2 tile (transpose into Ws[k][m])
        {
            int gr = mbase + wrow;
            float4 wv = make_float4(0.f, 0.f, 0.f, 0.f);
            if (gr < Kc) wv = *(const float4*)(&g_W2[gr * (2 * Hn) + k0 + wcol]);
            Ws[wcol + 0][wrow] = wv.x;
            Ws[wcol + 1][wrow] = wv.y;
            Ws[wcol + 2][wrow] = wv.z;
            Ws[wcol + 3][wrow] = wv.w;
        }
        // V tile: rows select A-half or B-half of Y
        {
            int kk = k0 + vrow;
            const float* src = (kk < Hn) ? (Ya + (size_t)kk * Ch)
                                         : (Yb2 + (size_t)(kk - Hn) * Ch);
            *(float4*)(&Vs[vrow][vcol]) = *(const float4*)(&src[vcol]);
        }
        __syncthreads();

#pragma unroll
        for (int p = 0; p < BK2; p++) {
            float4 w4 = *(const float4*)(&Ws[p][ty * 4]);
            float4 v4 = *(const float4*)(&Vs[p][tx * 4]);
            float rw[4] = {w4.x, w4.y, w4.z, w4.w};
            float rv[4] = {v4.x, v4.y, v4.z, v4.w};
#pragma unroll
            for (int i = 0; i < 4; i++)
#pragma unroll
                for (int j = 0; j < 4; j++) acc[i][j] += rw[i] * rv[j];
        }
        __syncthreads();
    }

    const size_t obase = (size_t)(b * Kc + k1) * Kc * Ch;
#pragma unroll
    for (int i = 0; i < 4; i++) {
        int k2 = mbase + ty * 4 + i;
        if (k2 < Kc) {
            *(float4*)(&out[obase + (size_t)k2 * Ch + tx * 4]) =
                make_float4(acc[i][0], acc[i][1], acc[i][2], acc[i][3]);
        }
    }
}

// ---------------------------------------------------------------------------
extern "C" void kernel_launch(void* const* d_in, const int* in_sizes, int n_in,
                              void* d_out, int out_size) {
    const float* X = (const float*)d_in[0];
    float* out = (float*)d_out;

    sp_init<<<(Kc * Hn + 255) / 256, 256>>>();

    dim3 g1(NC / BN1, (R1 + BM1 - 1) / BM1, Bt);   // (128, 4, 16)
    sp_stage1<<<g1, 256>>>(X);

    dim3 g2((Kc + BM2 - 1) / BM2, Kc, Bt);          // (4, 217, 16)
    sp_stage2<<<g2, 256>>>(out);
}

// round 5
// speedup vs baseline: 2.1751x; 2.1751x over previous
#include <cuda_runtime.h>
#include <cuda_bf16.h>
#include <cstdint>

// ============================================================================
// Spectral pooling as two split-bf16 GEMMs on the legacy tensor-core path
// (mma.sync m16n8k16 — plain sm_100 target has no tcgen05).
//   out = A X A^T - B X B^T   (per batch, per channel)
// Stage 1: Ys[(k1,c)][(half,n2)-split] = W1[(half,k1)][n1-stk] * Xs[(c,n2)][n1-stk]
// Stage 2: out[k2][(k1,c)]             = W2[k2][(half,n2)-stk] * Ys
// Split bf16: v ~ v0 + v1; weights K-stacked [a0|a0|a1]; data dedup'd [x0|x1]
// with chunk remap re-reading x0 against the a1 segment.
// ============================================================================

namespace {
constexpr int Hn = 256, Kc = 217, Bt = 16, Ch = 64;
constexpr int K1A = 768;    // stage-1 A K (3*256)
constexpr int K1B = 512;    // stage-1 B K (x0|x1)
constexpr int K2A = 1536;   // stage-2 A K (3*512)
constexpr int K2B = 1024;   // stage-2 B K (y0|y1)
constexpr int NC1 = 16384;  // stage-1 N  (c*256 + n2)
constexpr int YR  = 14080;  // stage-2 N padded (110*128 >= 217*64=13888)
constexpr double PI_D = 3.14159265358979323846;
}

__device__ __nv_bfloat16 g_W1s[512 * K1A];              // rows>=434 stay 0
__device__ __nv_bfloat16 g_W2s[256 * K2A];              // rows>=217 stay 0
__device__ __nv_bfloat16 g_Xs[(size_t)Bt * NC1 * K1B];  // stage-1 B operand
__device__ __nv_bfloat16 g_Ys[(size_t)Bt * YR * K2B];   // stage-2 B (pad rows 0)

#define SW128(x) ((x) ^ (((x) >> 3) & 0x70))

// ---------------- PTX helpers (all sm_80-era, valid on sm_100) --------------
__device__ __forceinline__ uint32_t smem_u32(const void* p) {
    uint32_t a;
    asm("{ .reg .u64 t; cvta.to.shared.u64 t, %1; cvt.u32.u64 %0, t; }" : "=r"(a) : "l"(p));
    return a;
}
__device__ __forceinline__ void cp16(uint32_t dst, const void* src) {
    asm volatile("cp.async.cg.shared.global [%0], [%1], 16;" :: "r"(dst), "l"(src));
}
__device__ __forceinline__ void cp_commit() { asm volatile("cp.async.commit_group;"); }
template <int N>
__device__ __forceinline__ void cp_wait() {
    asm volatile("cp.async.wait_group %0;" :: "n"(N));
}
__device__ __forceinline__ void ldm_x4(uint32_t* r, uint32_t addr) {
    asm volatile("ldmatrix.sync.aligned.m8n8.x4.shared.b16 {%0,%1,%2,%3}, [%4];"
                 : "=r"(r[0]), "=r"(r[1]), "=r"(r[2]), "=r"(r[3]) : "r"(addr));
}
__device__ __forceinline__ void mma16816(float* c, const uint32_t* a,
                                         uint32_t b0, uint32_t b1) {
    asm volatile(
        "mma.sync.aligned.m16n8k16.row.col.f32.bf16.bf16.f32 "
        "{%0,%1,%2,%3}, {%4,%5,%6,%7}, {%8,%9}, {%0,%1,%2,%3};"
        : "+f"(c[0]), "+f"(c[1]), "+f"(c[2]), "+f"(c[3])
        : "r"(a[0]), "r"(a[1]), "r"(a[2]), "r"(a[3]), "r"(b0), "r"(b1));
}

// ---------------- init: split-bf16 weight tables ----------------------------
__global__ void sp_init() {
    int idx = blockIdx.x * blockDim.x + threadIdx.x;
    if (idx >= Kc * Hn) return;
    int k = idx / Hn, n = idx - (idx / Hn) * Hn;
    double ph = PI_D * ((double)k / (double)Kc - (double)n / (double)Hn);
    double D = (k == 0 && n == 0) ? 1.0 : sin(217.0 * ph) / (sin(ph) * 217.0);
    double ang = 2.0 * PI_D * (double)n / (double)Hn;
    float a = (float)(D * cos(ang));
    float b = (float)(D * sin(ang));
    __nv_bfloat16 a0 = __float2bfloat16(a);
    __nv_bfloat16 a1 = __float2bfloat16(a - __bfloat162float(a0));
    __nv_bfloat16 b0 = __float2bfloat16(b);
    __nv_bfloat16 b1 = __float2bfloat16(b - __bfloat162float(b0));
    float nb = -b;
    __nv_bfloat16 nb0 = __float2bfloat16(nb);
    __nv_bfloat16 nb1 = __float2bfloat16(nb - __bfloat162float(nb0));
    // W1s rows: A rows [a0|a0|a1], B rows [b0|b0|b1] (chunks pair with x0,x1,x0)
    size_t ra = (size_t)k * K1A, rb = (size_t)(Kc + k) * K1A;
    g_W1s[ra + n] = a0;  g_W1s[ra + 256 + n] = a0;  g_W1s[ra + 512 + n] = a1;
    g_W1s[rb + n] = b0;  g_W1s[rb + 256 + n] = b0;  g_W1s[rb + 512 + n] = b1;
    // W2s rows: [w0(512) | w0(512) | w1(512)],  w = [A | -B] over (half,n2)
    size_t r2 = (size_t)k * K2A;
    g_W2s[r2 + n]        = a0;  g_W2s[r2 + 256 + n]  = nb0;
    g_W2s[r2 + 512 + n]  = a0;  g_W2s[r2 + 768 + n]  = nb0;
    g_W2s[r2 + 1024 + n] = a1;  g_W2s[r2 + 1280 + n] = nb1;
}

// ---------------- transpose+split: X -> Xs[b][c*256+n2][x0|x1] --------------
__global__ __launch_bounds__(256) void sp_transpose(const float* __restrict__ X) {
    __shared__ float tile[32][65];
    const int n2  = blockIdx.x;   // 0..255
    const int n1g = blockIdx.y;   // 0..7
    const int b   = blockIdx.z;
    const int t   = threadIdx.x;
    const float* src = X + ((size_t)(b * Hn + n1g * 32)) * NC1 + n2 * 64;
#pragma unroll
    for (int p = 0; p < 8; p++) {
        int idx = p * 256 + t;
        int r = idx >> 6, col = idx & 63;
        tile[r][col] = src[(size_t)r * NC1 + col];
    }
    __syncthreads();
    const int c = t >> 2, part = t & 3, i0 = part * 8;
    __nv_bfloat16* dst =
        g_Xs + ((size_t)b * NC1 + c * 256 + n2) * K1B + n1g * 32 + i0;
    __align__(16) __nv_bfloat16 h0[8], h1[8];
#pragma unroll
    for (int i = 0; i < 8; i++) {
        float v = tile[i0 + i][c];
        h0[i] = __float2bfloat16(v);
        h1[i] = __float2bfloat16(v - __bfloat162float(h0[i]));
    }
    *(uint4*)(dst)       = *(const uint4*)h0;
    *(uint4*)(dst + 256) = *(const uint4*)h1;
}

// ---------------- warp-MMA GEMM: CTA 128x128, K-chunk 64, double-buffered ---
// SMEM: per buf A 128x128B (16KB) + B 128x128B (16KB); 2 bufs = 64KB dynamic.
constexpr int TILE_B = 16384;
constexpr int SMEM_GEMM = 4 * TILE_B;

template <int STAGE>
__global__ __launch_bounds__(256, 2) void sp_gemm(float* __restrict__ out) {
    extern __shared__ char smem[];
    const uint32_t sb = smem_u32(smem);
    const int tid = threadIdx.x, lane = tid & 31, wid = tid >> 5;
    const int warp_m = wid >> 2, warp_n = wid & 3;  // 2 x 4 warp grid
    const int mt = blockIdx.x, nt = blockIdx.y, b = blockIdx.z;

    constexpr int KTA = (STAGE == 1) ? K1A : K2A;
    constexpr int KTB = (STAGE == 1) ? K1B : K2B;
    constexpr int NCH = KTA / 64;   // 12 / 24
    constexpr int NB  = KTB / 64;   // 8 / 16
    const __nv_bfloat16* Arow = ((STAGE == 1) ? g_W1s : g_W2s) + (size_t)(mt * 128) * KTA;
    const __nv_bfloat16* Brow = ((STAGE == 1) ? (g_Xs + (size_t)b * NC1 * K1B)
                                              : (g_Ys + (size_t)b * YR * K2B))
                                + (size_t)(nt * 128) * KTB;

    // per-thread cp.async source rows: 4 x 16B for A, 4 for B per chunk
    const int cr = tid >> 1;            // 0..127 (row), two threads per row
    const int cs = (tid & 1) * 4;       // 16B slot 0..3 / 4..7

    float acc[4][4][4];
#pragma unroll
    for (int i = 0; i < 4; i++)
#pragma unroll
        for (int j = 0; j < 4; j++)
#pragma unroll
            for (int q = 0; q < 4; q++) acc[i][j][q] = 0.f;

    auto prefetch = [&](int kc) {
        const int kb = (kc < NB) ? kc : kc - NB;  // dedup remap for B
        const uint32_t abase = sb + (kc & 1) * 2 * TILE_B;
        const uint32_t bbase = abase + TILE_B;
        const __nv_bfloat16* ga = Arow + (size_t)cr * KTA + kc * 64 + cs * 8;
        const __nv_bfloat16* gb = Brow + (size_t)cr * KTB + kb * 64 + cs * 8;
#pragma unroll
        for (int s = 0; s < 4; s++) {
            cp16(abase + SW128(cr * 128 + (cs + s) * 16), ga + s * 8);
            cp16(bbase + SW128(cr * 128 + (cs + s) * 16), gb + s * 8);
        }
        cp_commit();
    };

    prefetch(0);
    for (int kc = 0; kc < NCH; kc++) {
        if (kc + 1 < NCH) prefetch(kc + 1);
        if (kc + 1 < NCH) cp_wait<1>(); else cp_wait<0>();
        __syncthreads();
        const uint32_t abase = sb + (kc & 1) * 2 * TILE_B;
        const uint32_t bbase = abase + TILE_B;
        // lane-fixed parts of ldmatrix addresses
        const int arow = warp_m * 64 + (lane & 7) + ((lane >> 3) & 1) * 8;
        const int akof = ((lane >> 4) & 1) * 16;
        const int brow = warp_n * 32 + (lane & 7) + ((lane >> 4) & 1) * 8;
        const int bkof = ((lane >> 3) & 1) * 16;
#pragma unroll
        for (int ks = 0; ks < 4; ks++) {
            const int kb0 = ks * 32;
            uint32_t af[4][4];
#pragma unroll
            for (int mi = 0; mi < 4; mi++)
                ldm_x4(af[mi], abase + SW128((arow + mi * 16) * 128 + kb0 + akof));
            uint32_t bf[2][4];
#pragma unroll
            for (int nj = 0; nj < 2; nj++)
                ldm_x4(bf[nj], bbase + SW128((brow + nj * 16) * 128 + kb0 + bkof));
#pragma unroll
            for (int mi = 0; mi < 4; mi++)
#pragma unroll
                for (int ni = 0; ni < 4; ni++)
                    mma16816(acc[mi][ni], af[mi],
                             bf[ni >> 1][(ni & 1) * 2], bf[ni >> 1][(ni & 1) * 2 + 1]);
        }
        __syncthreads();
    }

    // ---------------- epilogue (registers -> global) ----------------
    const int r0 = lane >> 2;          // c-frag rows r0, r0+8
    const int c0 = 2 * (lane & 3);     // c-frag col pair
    if (STAGE == 1) {
        __nv_bfloat16* Yb = g_Ys + (size_t)b * YR * K2B;
#pragma unroll
        for (int mi = 0; mi < 4; mi++) {
#pragma unroll
            for (int half_r = 0; half_r < 2; half_r++) {
                const int gr = mt * 128 + warp_m * 64 + mi * 16 + r0 + half_r * 8;
                if (gr >= 434) continue;
                const int hf = (gr >= Kc) ? 1 : 0;
                const int k1 = gr - hf * Kc;
#pragma unroll
                for (int ni = 0; ni < 4; ni++) {
                    const int gn = nt * 128 + warp_n * 32 + ni * 8 + c0;
                    const int c = gn >> 8, n2 = gn & 255;
                    float v0 = acc[mi][ni][half_r * 2 + 0];
                    float v1 = acc[mi][ni][half_r * 2 + 1];
                    __nv_bfloat16 h0a = __float2bfloat16(v0);
                    __nv_bfloat16 h0b = __float2bfloat16(v1);
                    __nv_bfloat16 h1a = __float2bfloat16(v0 - __bfloat162float(h0a));
                    __nv_bfloat16 h1b = __float2bfloat16(v1 - __bfloat162float(h0b));
                    __nv_bfloat16* d =
                        Yb + ((size_t)k1 * 64 + c) * K2B + hf * 256 + n2;
                    __nv_bfloat162 p0; p0.x = h0a; p0.y = h0b;
                    __nv_bfloat162 p1; p1.x = h1a; p1.y = h1b;
                    *(__nv_bfloat162*)(d)       = p0;   // y0 segment
                    *(__nv_bfloat162*)(d + 512) = p1;   // y1 segment
                }
            }
        }
    } else {
#pragma unroll
        for (int mi = 0; mi < 4; mi++) {
#pragma unroll
            for (int half_r = 0; half_r < 2; half_r++) {
                const int k2 = mt * 128 + warp_m * 64 + mi * 16 + r0 + half_r * 8;
                if (k2 >= Kc) continue;
#pragma unroll
                for (int ni = 0; ni < 4; ni++) {
                    const int gn = nt * 128 + warp_n * 32 + ni * 8 + c0;
                    const int k1 = gn >> 6, c = gn & 63;
                    if (k1 >= Kc) continue;
                    float2 v = make_float2(acc[mi][ni][half_r * 2 + 0],
                                           acc[mi][ni][half_r * 2 + 1]);
                    *(float2*)(out + ((size_t)(b * Kc + k1) * Kc + k2) * Ch + c) = v;
                }
            }
        }
    }
}

// ---------------------------------------------------------------------------
extern "C" void kernel_launch(void* const* d_in, const int* in_sizes, int n_in,
                              void* d_out, int out_size) {
    const float* X = (const float*)d_in[0];
    float* out = (float*)d_out;

    cudaFuncSetAttribute(sp_gemm<1>, cudaFuncAttributeMaxDynamicSharedMemorySize, SMEM_GEMM);
    cudaFuncSetAttribute(sp_gemm<2>, cudaFuncAttributeMaxDynamicSharedMemorySize, SMEM_GEMM);

    sp_init<<<(Kc * Hn + 255) / 256, 256>>>();
    sp_transpose<<<dim3(256, 8, Bt), 256>>>(X);
    sp_gemm<1><<<dim3(4, 128, Bt), 256, SMEM_GEMM>>>(nullptr);  // Ys = W1 * Xs^T
    sp_gemm<2><<<dim3(2, 110, Bt), 256, SMEM_GEMM>>>(out);      // out = W2 * Ys^T
}

// round 8
// speedup vs baseline: 2.7547x; 1.2665x over previous
#include <cuda_runtime.h>
#include <cuda_bf16.h>
#include <cstdint>

// ============================================================================
// Spectral pooling as two split-bf16 GEMMs on the legacy tensor-core path
// (mma.sync m16n8k16 — plain sm_100 target, no tcgen05).
//   out = A X A^T - B X B^T   (per batch, per channel)
// Stage 1: Ys[(k1,c)][(half,n2)-split] = W1[(half,k1)][n1-stk] * Xs[(c,n2)][n1-stk]
// Stage 2: out[k2][(k1,c)]             = W2[k2][(half,n2)-stk] * Ys
// Split bf16: v ~ v0 + v1; weights K-stacked [a0|a0|a1]; data dedup'd [x0|x1]
// with chunk remap re-reading x0 against the a1 segment.
// R8: resubmit of R7 (warp tile m64n64, CTA 256x128, 2-stage pipeline).
// ============================================================================

namespace {
constexpr int Hn = 256, Kc = 217, Bt = 16, Ch = 64;
constexpr int K1A = 768;    // stage-1 A K (3*256)
constexpr int K1B = 512;    // stage-1 B K (x0|x1)
constexpr int K2A = 1536;   // stage-2 A K (3*512)
constexpr int K2B = 1024;   // stage-2 B K (y0|y1)
constexpr int NC1 = 16384;  // stage-1 N  (c*256 + n2)
constexpr int YR  = 14080;  // stage-2 N padded (110*128 >= 217*64=13888)
constexpr double PI_D = 3.14159265358979323846;
}

__device__ __nv_bfloat16 g_W1s[512 * K1A];              // rows>=434 stay 0
__device__ __nv_bfloat16 g_W2s[256 * K2A];              // rows>=217 stay 0
__device__ __nv_bfloat16 g_Xs[(size_t)Bt * NC1 * K1B];  // stage-1 B operand
__device__ __nv_bfloat16 g_Ys[(size_t)Bt * YR * K2B];   // stage-2 B (pad rows 0)

#define SW128(x) ((x) ^ (((x) >> 3) & 0x70))

// ---------------- PTX helpers ------------------------------------------------
__device__ __forceinline__ uint32_t smem_u32(const void* p) {
    uint32_t a;
    asm("{ .reg .u64 t; cvta.to.shared.u64 t, %1; cvt.u32.u64 %0, t; }" : "=r"(a) : "l"(p));
    return a;
}
__device__ __forceinline__ void cp16(uint32_t dst, const void* src) {
    asm volatile("cp.async.cg.shared.global [%0], [%1], 16;" :: "r"(dst), "l"(src));
}
__device__ __forceinline__ void cp_commit() { asm volatile("cp.async.commit_group;"); }
template <int N>
__device__ __forceinline__ void cp_wait() {
    asm volatile("cp.async.wait_group %0;" :: "n"(N));
}
__device__ __forceinline__ void ldm_x4(uint32_t* r, uint32_t addr) {
    asm volatile("ldmatrix.sync.aligned.m8n8.x4.shared.b16 {%0,%1,%2,%3}, [%4];"
                 : "=r"(r[0]), "=r"(r[1]), "=r"(r[2]), "=r"(r[3]) : "r"(addr));
}
__device__ __forceinline__ void mma16816(float* c, const uint32_t* a,
                                         uint32_t b0, uint32_t b1) {
    asm volatile(
        "mma.sync.aligned.m16n8k16.row.col.f32.bf16.bf16.f32 "
        "{%0,%1,%2,%3}, {%4,%5,%6,%7}, {%8,%9}, {%0,%1,%2,%3};"
        : "+f"(c[0]), "+f"(c[1]), "+f"(c[2]), "+f"(c[3])
        : "r"(a[0]), "r"(a[1]), "r"(a[2]), "r"(a[3]), "r"(b0), "r"(b1));
}

// ---------------- init: split-bf16 weight tables ----------------------------
__global__ void sp_init() {
    int idx = blockIdx.x * blockDim.x + threadIdx.x;
    if (idx >= Kc * Hn) return;
    int k = idx / Hn, n = idx - (idx / Hn) * Hn;
    double ph = PI_D * ((double)k / (double)Kc - (double)n / (double)Hn);
    double D = (k == 0 && n == 0) ? 1.0 : sin(217.0 * ph) / (sin(ph) * 217.0);
    double ang = 2.0 * PI_D * (double)n / (double)Hn;
    float a = (float)(D * cos(ang));
    float b = (float)(D * sin(ang));
    __nv_bfloat16 a0 = __float2bfloat16(a);
    __nv_bfloat16 a1 = __float2bfloat16(a - __bfloat162float(a0));
    __nv_bfloat16 b0 = __float2bfloat16(b);
    __nv_bfloat16 b1 = __float2bfloat16(b - __bfloat162float(b0));
    float nb = -b;
    __nv_bfloat16 nb0 = __float2bfloat16(nb);
    __nv_bfloat16 nb1 = __float2bfloat16(nb - __bfloat162float(nb0));
    size_t ra = (size_t)k * K1A, rb = (size_t)(Kc + k) * K1A;
    g_W1s[ra + n] = a0;  g_W1s[ra + 256 + n] = a0;  g_W1s[ra + 512 + n] = a1;
    g_W1s[rb + n] = b0;  g_W1s[rb + 256 + n] = b0;  g_W1s[rb + 512 + n] = b1;
    size_t r2 = (size_t)k * K2A;
    g_W2s[r2 + n]        = a0;  g_W2s[r2 + 256 + n]  = nb0;
    g_W2s[r2 + 512 + n]  = a0;  g_W2s[r2 + 768 + n]  = nb0;
    g_W2s[r2 + 1024 + n] = a1;  g_W2s[r2 + 1280 + n] = nb1;
}

// ---------------- transpose+split: X -> Xs[b][c*256+n2][x0|x1] --------------
__global__ __launch_bounds__(256) void sp_transpose(const float* __restrict__ X) {
    __shared__ float tile[32][65];
    const int n2  = blockIdx.x;   // 0..255
    const int n1g = blockIdx.y;   // 0..7
    const int b   = blockIdx.z;
    const int t   = threadIdx.x;
    const float* src = X + ((size_t)(b * Hn + n1g * 32)) * NC1 + n2 * 64;
#pragma unroll
    for (int p = 0; p < 8; p++) {
        int idx = p * 256 + t;
        int r = idx >> 6, col = idx & 63;
        tile[r][col] = src[(size_t)r * NC1 + col];
    }
    __syncthreads();
    const int c = t >> 2, part = t & 3, i0 = part * 8;
    __nv_bfloat16* dst =
        g_Xs + ((size_t)b * NC1 + c * 256 + n2) * K1B + n1g * 32 + i0;
    __align__(16) __nv_bfloat16 h0[8], h1[8];
#pragma unroll
    for (int i = 0; i < 8; i++) {
        float v = tile[i0 + i][c];
        h0[i] = __float2bfloat16(v);
        h1[i] = __float2bfloat16(v - __bfloat162float(h0[i]));
    }
    *(uint4*)(dst)       = *(const uint4*)h0;
    *(uint4*)(dst + 256) = *(const uint4*)h1;
}

// ---------------- warp-MMA GEMM: CTA 256x128, warp m64n64, double-buffered --
// SMEM per buf: A 256x128B (32KB) + B 128x128B (16KB) = 48KB; 2 bufs = 96KB.
constexpr int ST_BYTES = 49152;
constexpr int SMEM_GEMM = 2 * ST_BYTES;   // 98304

template <int STAGE>
__global__ __launch_bounds__(256, 1) void sp_gemm(float* __restrict__ out) {
    extern __shared__ char smem[];
    const uint32_t sb = smem_u32(smem);
    const int tid = threadIdx.x, lane = tid & 31, wid = tid >> 5;
    const int warp_m = wid >> 1, warp_n = wid & 1;   // 4 x 2 warp grid, m64n64
    const int mt = blockIdx.x, nt = blockIdx.y, b = blockIdx.z;

    constexpr int KTA = (STAGE == 1) ? K1A : K2A;
    constexpr int KTB = (STAGE == 1) ? K1B : K2B;
    constexpr int NCH = KTA / 64;   // 12 / 24
    constexpr int NB  = KTB / 64;   // 8 / 16
    const __nv_bfloat16* Arow = ((STAGE == 1) ? g_W1s : g_W2s) + (size_t)(mt * 256) * KTA;
    const __nv_bfloat16* Brow = ((STAGE == 1) ? (g_Xs + (size_t)b * NC1 * K1B)
                                              : (g_Ys + (size_t)b * YR * K2B))
                                + (size_t)(nt * 128) * KTB;

    float acc[4][8][4];
#pragma unroll
    for (int i = 0; i < 4; i++)
#pragma unroll
        for (int j = 0; j < 8; j++)
#pragma unroll
            for (int q = 0; q < 4; q++) acc[i][j][q] = 0.f;

    auto prefetch = [&](int kc) {
        const int kb = (kc < NB) ? kc : kc - NB;    // dedup remap for B
        const uint32_t abase = sb + (kc & 1) * ST_BYTES;
        const uint32_t bbase = abase + 32768;
        // A: 256 rows x 128B = 2048 16B slots; 8 per thread
#pragma unroll
        for (int p = 0; p < 8; p++) {
            int slot = p * 256 + tid;
            int r = slot >> 3, s = slot & 7;
            cp16(abase + SW128(r * 128 + s * 16),
                 Arow + (size_t)r * KTA + kc * 64 + s * 8);
        }
        // B: 128 rows x 128B = 1024 slots; 4 per thread
#pragma unroll
        for (int p = 0; p < 4; p++) {
            int slot = p * 256 + tid;
            int r = slot >> 3, s = slot & 7;
            cp16(bbase + SW128(r * 128 + s * 16),
                 Brow + (size_t)r * KTB + kb * 64 + s * 8);
        }
        cp_commit();
    };

    const int arow = warp_m * 64 + (lane & 7) + ((lane >> 3) & 1) * 8;
    const int akof = ((lane >> 4) & 1) * 16;
    const int brow = warp_n * 64 + (lane & 7) + ((lane >> 4) & 1) * 8;
    const int bkof = ((lane >> 3) & 1) * 16;

    prefetch(0);
    for (int kc = 0; kc < NCH; kc++) {
        if (kc + 1 < NCH) prefetch(kc + 1);
        if (kc + 1 < NCH) cp_wait<1>(); else cp_wait<0>();
        __syncthreads();
        const uint32_t abase = sb + (kc & 1) * ST_BYTES;
        const uint32_t bbase = abase + 32768;
#pragma unroll
        for (int ks = 0; ks < 4; ks++) {
            const int kb0 = ks * 32;
            uint32_t af[4][4];
#pragma unroll
            for (int mi = 0; mi < 4; mi++)
                ldm_x4(af[mi], abase + SW128((arow + mi * 16) * 128 + kb0 + akof));
            uint32_t bf[4][4];
#pragma unroll
            for (int nj = 0; nj < 4; nj++)
                ldm_x4(bf[nj], bbase + SW128((brow + nj * 16) * 128 + kb0 + bkof));
#pragma unroll
            for (int mi = 0; mi < 4; mi++)
#pragma unroll
                for (int ni = 0; ni < 8; ni++)
                    mma16816(acc[mi][ni], af[mi],
                             bf[ni >> 1][(ni & 1) * 2], bf[ni >> 1][(ni & 1) * 2 + 1]);
        }
        __syncthreads();
    }

    // ---------------- epilogue (registers -> global) ----------------
    const int r0 = lane >> 2;          // c-frag rows r0, r0+8
    const int c0 = 2 * (lane & 3);     // c-frag col pair
    if (STAGE == 1) {
        __nv_bfloat16* Yb = g_Ys + (size_t)b * YR * K2B;
#pragma unroll
        for (int mi = 0; mi < 4; mi++) {
#pragma unroll
            for (int half_r = 0; half_r < 2; half_r++) {
                const int gr = mt * 256 + warp_m * 64 + mi * 16 + r0 + half_r * 8;
                if (gr >= 434) continue;
                const int hf = (gr >= Kc) ? 1 : 0;
                const int k1 = gr - hf * Kc;
                __nv_bfloat16* rowbase =
                    Yb + (size_t)k1 * 64 * K2B + hf * 256;
#pragma unroll
                for (int ni = 0; ni < 8; ni++) {
                    const int gn = nt * 128 + warp_n * 64 + ni * 8 + c0;
                    const int c = gn >> 8, n2 = gn & 255;
                    float v0 = acc[mi][ni][half_r * 2 + 0];
                    float v1 = acc[mi][ni][half_r * 2 + 1];
                    __nv_bfloat16 h0a = __float2bfloat16(v0);
                    __nv_bfloat16 h0b = __float2bfloat16(v1);
                    __nv_bfloat16 h1a = __float2bfloat16(v0 - __bfloat162float(h0a));
                    __nv_bfloat16 h1b = __float2bfloat16(v1 - __bfloat162float(h0b));
                    __nv_bfloat16* d = rowbase + (size_t)c * K2B + n2;
                    __nv_bfloat162 p0; p0.x = h0a; p0.y = h0b;
                    __nv_bfloat162 p1; p1.x = h1a; p1.y = h1b;
                    *(__nv_bfloat162*)(d)       = p0;   // y0 segment
                    *(__nv_bfloat162*)(d + 512) = p1;   // y1 segment
                }
            }
        }
    } else {
#pragma unroll
        for (int mi = 0; mi < 4; mi++) {
#pragma unroll
            for (int half_r = 0; half_r < 2; half_r++) {
                const int k2 = mt * 256 + warp_m * 64 + mi * 16 + r0 + half_r * 8;
                if (k2 >= Kc) continue;
#pragma unroll
                for (int ni = 0; ni < 8; ni++) {
                    const int gn = nt * 128 + warp_n * 64 + ni * 8 + c0;
                    const int k1 = gn >> 6, c = gn & 63;
                    if (k1 >= Kc) continue;
                    float2 v = make_float2(acc[mi][ni][half_r * 2 + 0],
                                           acc[mi][ni][half_r * 2 + 1]);
                    *(float2*)(out + ((size_t)(b * Kc + k1) * Kc + k2) * Ch + c) = v;
                }
            }
        }
    }
}

// ---------------------------------------------------------------------------
extern "C" void kernel_launch(void* const* d_in, const int* in_sizes, int n_in,
                              void* d_out, int out_size) {
    const float* X = (const float*)d_in[0];
    float* out = (float*)d_out;

    cudaFuncSetAttribute(sp_gemm<1>, cudaFuncAttributeMaxDynamicSharedMemorySize, SMEM_GEMM);
    cudaFuncSetAttribute(sp_gemm<2>, cudaFuncAttributeMaxDynamicSharedMemorySize, SMEM_GEMM);

    sp_init<<<(Kc * Hn + 255) / 256, 256>>>();
    sp_transpose<<<dim3(256, 8, Bt), 256>>>(X);
    sp_gemm<1><<<dim3(2, 128, Bt), 256, SMEM_GEMM>>>(nullptr);  // Ys = W1 * Xs^T
    sp_gemm<2><<<dim3(1, 110, Bt), 256, SMEM_GEMM>>>(out);      // out = W2 * Ys^T
}